// round 11
// baseline (speedup 1.0000x reference)
#include <cuda_runtime.h>
#include <cuda_fp16.h>
#include <math.h>
#include <stdint.h>

// Problem constants (GraphAttentionLayer: B=2, N=2048, D_IN=256, H=8, DH=32)
#define BB   2
#define NN   2048
#define DIN  256
#define HH   8
#define DHH  32
#define MROWS (BB*NN)   // 4096
#define BH    (BB*HH)   // 16
#define KT    128       // keys per tile
#define NTILE (NN/KT)   // 16

// ---------------- scratch (device globals; no allocation allowed) ----------
__device__ float g_att[(size_t)BB*NN*HH*DHH]; // (b,n,h,d)

__device__ uint4 g_Qb[(size_t)BH*NN*DHH/8];   // fp16 Q (scaled by log2e/sqrt(dh))
__device__ uint4 g_Kb[(size_t)BH*NN*DHH/8];   // fp16 K, row-major (n, d)
__device__ uint4 g_Vt[(size_t)BH*DHH*NN/8];   // fp16 V^T, (d, n)
__device__ uint4 g_mask[(size_t)BB*NN*16];    // adjacency bitmask: 16 uint4/row

// ---------------- helpers ---------------------------------------------------
static __device__ __forceinline__ uint32_t smem_u32(const void* p){
    uint32_t a;
    asm("{ .reg .u64 t; cvta.to.shared.u64 t, %1; cvt.u32.u64 %0, t; }" : "=r"(a) : "l"(p));
    return a;
}
#define LDMX4(r0,r1,r2,r3,addr) \
    asm volatile("ldmatrix.sync.aligned.m8n8.x4.shared.b16 {%0,%1,%2,%3}, [%4];" \
        : "=r"(r0),"=r"(r1),"=r"(r2),"=r"(r3) : "r"(addr))
#define MMA_F16(c0,c1,c2,c3,a0,a1,a2,a3,b0,b1) \
    asm volatile("mma.sync.aligned.m16n8k16.row.col.f32.f16.f16.f32 " \
        "{%0,%1,%2,%3}, {%4,%5,%6,%7}, {%8,%9}, {%0,%1,%2,%3};" \
        : "+f"(c0),"+f"(c1),"+f"(c2),"+f"(c3) \
        : "r"(a0),"r"(a1),"r"(a2),"r"(a3), "r"(b0),"r"(b1))
static __device__ __forceinline__ uint32_t f16x2_of(float hi, float lo){
    uint32_t r;
    asm("cvt.rn.satfinite.f16x2.f32 %0, %1, %2;" : "=r"(r) : "f"(hi), "f"(lo));
    return r;
}
#define CP16(dst, src) \
    asm volatile("cp.async.cg.shared.global [%0], [%1], 16;" :: "r"(dst), "l"(src) : "memory")
#define CP_COMMIT() asm volatile("cp.async.commit_group;" ::: "memory")
#define CP_WAIT0()  asm volatile("cp.async.wait_group 0;" ::: "memory")

// ============================================================================
// QKV projection, split-fp16 HMMA, direct fp16 image emit.
// grid (64, 2, 3), block 256. z selects {Wq->Qb, Wk->Kb, Wv->Vt}.
// ============================================================================
__global__ void __launch_bounds__(256) qkvh_kernel(
        const float* __restrict__ X, const float* __restrict__ Wq,
        const float* __restrict__ Wk, const float* __restrict__ Wv)
{
    const float* W = (blockIdx.z == 0) ? Wq : (blockIdx.z == 1) ? Wk : Wv;

    __shared__ __align__(16) __half sAh[64 * 72];
    __shared__ __align__(16) __half sAl[64 * 72];
    __shared__ __align__(16) __half sW [128 * 72];

    const int tid = threadIdx.x, w = tid >> 5, lane = tid & 31;
    const int wm = w >> 1, wn = w & 1;
    const int m0 = blockIdx.x * 64, n0 = blockIdx.y * 128;

    float c[8][4];
    #pragma unroll
    for (int i = 0; i < 8; i++)
        #pragma unroll
        for (int j = 0; j < 4; j++) c[i][j] = 0.0f;

    const uint32_t sAhB = smem_u32(sAh), sAlB = smem_u32(sAl), sWB = smem_u32(sW);
    const int arow = wm * 16 + (lane & 7) + ((lane >> 3) & 1) * 8;
    const uint32_t aoff  = (uint32_t)arow * 144 + ((lane >> 4) & 1) * 16;
    const uint32_t boff0 = (uint32_t)(wn * 64 + (lane & 7)) * 144 + ((lane >> 3) & 3) * 16;

    for (int chunk = 0; chunk < 4; chunk++) {
        const int k0 = chunk * 64;
        __syncthreads();
        {
            int r = tid >> 2, cg = (tid & 3) * 16;
            const float4* asrc = (const float4*)&X[(size_t)(m0 + r) * DIN + k0 + cg];
            #pragma unroll
            for (int j = 0; j < 4; j++) {
                float4 v = asrc[j];
                __half hx = __float2half(v.x), hy = __float2half(v.y);
                __half hz = __float2half(v.z), hw = __float2half(v.w);
                *(__half2*)&sAh[r*72 + cg + 4*j]     = __halves2half2(hx, hy);
                *(__half2*)&sAh[r*72 + cg + 4*j + 2] = __halves2half2(hz, hw);
                *(__half2*)&sAl[r*72 + cg + 4*j]     = __halves2half2(
                    __float2half(v.x - __half2float(hx)), __float2half(v.y - __half2float(hy)));
                *(__half2*)&sAl[r*72 + cg + 4*j + 2] = __halves2half2(
                    __float2half(v.z - __half2float(hz)), __float2half(v.w - __half2float(hw)));
            }
            int r2 = tid >> 1, cg2 = (tid & 1) * 32;
            const float4* wsrc = (const float4*)&W[(size_t)(n0 + r2) * DIN + k0 + cg2];
            #pragma unroll
            for (int j = 0; j < 8; j++) {
                float4 v = wsrc[j];
                *(__half2*)&sW[r2*72 + cg2 + 4*j]     = __halves2half2(__float2half(v.x), __float2half(v.y));
                *(__half2*)&sW[r2*72 + cg2 + 4*j + 2] = __halves2half2(__float2half(v.z), __float2half(v.w));
            }
        }
        __syncthreads();

        #pragma unroll
        for (int kk2 = 0; kk2 < 2; kk2++) {
            uint32_t ah0[4], ah1[4], al0[4], al1[4];
            LDMX4(ah0[0], ah0[1], ah0[2], ah0[3], sAhB + aoff + kk2 * 64);
            LDMX4(ah1[0], ah1[1], ah1[2], ah1[3], sAhB + aoff + kk2 * 64 + 32);
            LDMX4(al0[0], al0[1], al0[2], al0[3], sAlB + aoff + kk2 * 64);
            LDMX4(al1[0], al1[1], al1[2], al1[3], sAlB + aoff + kk2 * 64 + 32);
            #pragma unroll
            for (int nt = 0; nt < 8; nt++) {
                uint32_t b0, b1, b2, b3;
                LDMX4(b0, b1, b2, b3, sWB + boff0 + nt * 1152 + kk2 * 64);
                MMA_F16(c[nt][0], c[nt][1], c[nt][2], c[nt][3],
                        ah0[0], ah0[1], ah0[2], ah0[3], b0, b1);
                MMA_F16(c[nt][0], c[nt][1], c[nt][2], c[nt][3],
                        ah1[0], ah1[1], ah1[2], ah1[3], b2, b3);
                MMA_F16(c[nt][0], c[nt][1], c[nt][2], c[nt][3],
                        al0[0], al0[1], al0[2], al0[3], b0, b1);
                MMA_F16(c[nt][0], c[nt][1], c[nt][2], c[nt][3],
                        al1[0], al1[1], al1[2], al1[3], b2, b3);
            }
        }
    }

    // Q pre-scale folds log2(e) so attention can use exp2 directly.
    const float scale = (blockIdx.z == 0) ? 0.2550512985f : 1.0f;  // log2e/sqrt(32)
    const int mrow = m0 + wm * 16 + (lane >> 2);
    const int b = mrow >> 11, n = mrow & (NN - 1);
    __half* Vt = (__half*)g_Vt;
    __half2* QK2 = (blockIdx.z == 0) ? (__half2*)g_Qb : (__half2*)g_Kb;

    #pragma unroll
    for (int nt = 0; nt < 8; nt++) {
        const int o = n0 + wn * 64 + nt * 8 + 2 * (lane & 3);
        const int h = o >> 5, d = o & 31, bh = b * HH + h;
        if (blockIdx.z < 2) {
            QK2[(((size_t)bh * NN + n) * DHH + d) >> 1] =
                __halves2half2(__float2half(c[nt][0] * scale), __float2half(c[nt][1] * scale));
            QK2[(((size_t)bh * NN + n + 8) * DHH + d) >> 1] =
                __halves2half2(__float2half(c[nt][2] * scale), __float2half(c[nt][3] * scale));
        } else {
            Vt[((size_t)bh * DHH + d)     * NN + n]     = __float2half(c[nt][0]);
            Vt[((size_t)bh * DHH + d + 1) * NN + n]     = __float2half(c[nt][1]);
            Vt[((size_t)bh * DHH + d)     * NN + n + 8] = __float2half(c[nt][2]);
            Vt[((size_t)bh * DHH + d + 1) * NN + n + 8] = __float2half(c[nt][3]);
        }
    }
}

// ---------------- mask: adjacency -> bitmask -------------------------------
__global__ void __launch_bounds__(256) mask_kernel(const float* __restrict__ adj)
{
    int idx = blockIdx.x * 256 + threadIdx.x;   // over BB*NN*64 words
    int b = idx >> 17, rem = idx & 131071, n = rem >> 6, w = rem & 63;
    const float4* a4 = (const float4*)(adj + ((size_t)b * NN + n) * NN + w * 32);
    uint32_t m = 0;
    #pragma unroll
    for (int i = 0; i < 8; i++) {
        float4 v = a4[i];
        m |= (v.x != 0.0f ? 1u : 0u) << (i * 4 + 0);
        m |= (v.y != 0.0f ? 1u : 0u) << (i * 4 + 1);
        m |= (v.z != 0.0f ? 1u : 0u) << (i * 4 + 2);
        m |= (v.w != 0.0f ? 1u : 0u) << (i * 4 + 3);
    }
    ((uint32_t*)g_mask)[idx] = m;
}

// ============================================================================
// HMMA flash attention: fp16 operands, fp32 accum, exp2 softmax,
// cp.async double-buffered K/V/mask staging.
// grid 256 = bh*16 + qtile, block 256 (8 warps x 16 query rows).
// ============================================================================
__global__ void __launch_bounds__(256, 2) attn_kernel()
{
    __shared__ __align__(16) __half sK[2][128 * 40];   // 2 x 10240 B
    __shared__ __align__(16) __half sVt[2][32 * 136];  // 2 x  8704 B
    __shared__ __align__(16) uint4 sMask[2][8][16];    // 2 x  2048 B

    const int tid  = threadIdx.x;
    const int w    = tid >> 5;
    const int lane = tid & 31;
    const int bh   = blockIdx.x >> 4, qt = blockIdx.x & 15;
    const int b    = bh >> 3, h = bh & 7;
    const int q0   = qt * 128 + w * 16;

    const uint32_t kBufB[2] = { smem_u32(sK[0]),    smem_u32(sK[1]) };
    const uint32_t vBufB[2] = { smem_u32(sVt[0]),   smem_u32(sVt[1]) };
    const uint32_t mBufB[2] = { smem_u32(sMask[0]), smem_u32(sMask[1]) };

    // ---- stage Q tile into sK[0], load A frags -----------------------------
    {
        const uint4* src = g_Qb + ((size_t)bh * NN + qt * 128) * 4;
        int r = tid >> 1, hf = tid & 1;
        uint4* dst = (uint4*)(sK[0] + r * 40) + hf * 2;
        dst[0] = src[r * 4 + hf * 2];
        dst[1] = src[r * 4 + hf * 2 + 1];
    }
    __syncthreads();

    uint32_t aq[2][4];
    {
        const int arow = (lane & 7) + ((lane >> 3) & 1) * 8 + w * 16;
        const uint32_t kb = ((lane >> 4) & 1) * 16;
        uint32_t a0 = kBufB[0] + arow * 80 + kb;
        LDMX4(aq[0][0], aq[0][1], aq[0][2], aq[0][3], a0);
        LDMX4(aq[1][0], aq[1][1], aq[1][2], aq[1][3], a0 + 32);
    }
    __syncthreads();   // all warps own their frags before tile0 overwrites sK[0]

    const uint32_t kLane = (lane & 7) * 80 + ((lane >> 3) & 3) * 16;
    const uint32_t vLane = ((lane & 7) + ((lane >> 4) & 1) * 8) * 272
                         + ((lane >> 3) & 1) * 16;

    // ---- cp.async tile stager ----------------------------------------------
    auto stage = [&](int t, int buf) {
        const char* ksrc = (const char*)(g_Kb + ((size_t)bh * NN + t * 128) * 4);
        int r = tid >> 1, hf = tid & 1;
        uint32_t kdst = kBufB[buf] + r * 80 + hf * 32;
        CP16(kdst,      ksrc + r * 64 + hf * 32);
        CP16(kdst + 16, ksrc + r * 64 + hf * 32 + 16);
        const char* vsrc = (const char*)(g_Vt + (size_t)bh * DHH * (NN / 8) + (size_t)t * 16);
        int vr = tid >> 3, oct = tid & 7;
        uint32_t vdst = vBufB[buf] + vr * 272 + oct * 32;
        CP16(vdst,      vsrc + vr * (NN * 2) + oct * 32);
        CP16(vdst + 16, vsrc + vr * (NN * 2) + oct * 32 + 16);
        if (tid < 128) {
            int ww = tid >> 4, l = tid & 15;
            const char* msrc = (const char*)(g_mask + ((size_t)b * NN + qt * 128 + ww * 16 + l) * 16 + t);
            CP16(mBufB[buf] + (ww * 16 + l) * 16, msrc);
        }
        CP_COMMIT();
    };

    stage(0, 0);

    float o[4][4];
    #pragma unroll
    for (int i = 0; i < 4; i++)
        #pragma unroll
        for (int j = 0; j < 4; j++) o[i][j] = 0.0f;
    float sA = 0.0f, sB = 0.0f;

    for (int t = 0; t < NTILE; t++) {
        const int buf = t & 1;
        CP_WAIT0();
        __syncthreads();
        if (t < NTILE - 1) stage(t + 1, buf ^ 1);   // overlap with compute below

        const uint32_t kBase = kBufB[buf] + kLane;
        const uint32_t vBase = vBufB[buf] + vLane;
        uint4 mA = sMask[buf][w][lane >> 2];
        uint4 mB = sMask[buf][w][8 + (lane >> 2)];

        // ---- QK^T scores (already in log2 domain via Q pre-scale) ----
        float c[16][4];
        #pragma unroll
        for (int nb = 0; nb < 16; nb++) {
            c[nb][0] = c[nb][1] = c[nb][2] = c[nb][3] = 0.0f;
            uint32_t b0, b1, b2, b3;
            LDMX4(b0, b1, b2, b3, kBase + nb * 640);
            MMA_F16(c[nb][0], c[nb][1], c[nb][2], c[nb][3],
                    aq[0][0], aq[0][1], aq[0][2], aq[0][3], b0, b1);
            MMA_F16(c[nb][0], c[nb][1], c[nb][2], c[nb][3],
                    aq[1][0], aq[1][1], aq[1][2], aq[1][3], b2, b3);
        }

        // ---- mask + exp2 + rowsum ----
        const int bshift = 2 * (lane & 3);
        #pragma unroll
        for (int nb = 0; nb < 16; nb++) {
            uint32_t wA = (nb < 4) ? mA.x : (nb < 8) ? mA.y : (nb < 12) ? mA.z : mA.w;
            uint32_t wB = (nb < 4) ? mB.x : (nb < 8) ? mB.y : (nb < 12) ? mB.z : mB.w;
            int s0 = (nb & 3) * 8 + bshift;
            float p0 = ((wA >> s0) & 1u)     ? exp2f(c[nb][0]) : 0.0f;
            float p1 = ((wA >> (s0+1)) & 1u) ? exp2f(c[nb][1]) : 0.0f;
            float p2 = ((wB >> s0) & 1u)     ? exp2f(c[nb][2]) : 0.0f;
            float p3 = ((wB >> (s0+1)) & 1u) ? exp2f(c[nb][3]) : 0.0f;
            c[nb][0] = p0; c[nb][1] = p1; c[nb][2] = p2; c[nb][3] = p3;
            sA += p0 + p1;
            sB += p2 + p3;
        }

        // ---- P @ V^T ----
        #pragma unroll
        for (int j = 0; j < 8; j++) {
            uint32_t p0 = f16x2_of(c[2*j][1],   c[2*j][0]);
            uint32_t p1 = f16x2_of(c[2*j][3],   c[2*j][2]);
            uint32_t p2 = f16x2_of(c[2*j+1][1], c[2*j+1][0]);
            uint32_t p3 = f16x2_of(c[2*j+1][3], c[2*j+1][2]);
            uint32_t v0, v1, v2, v3;
            LDMX4(v0, v1, v2, v3, vBase + j * 32);
            MMA_F16(o[0][0], o[0][1], o[0][2], o[0][3], p0, p1, p2, p3, v0, v1);
            MMA_F16(o[1][0], o[1][1], o[1][2], o[1][3], p0, p1, p2, p3, v2, v3);
            LDMX4(v0, v1, v2, v3, vBase + 16 * 272 + j * 32);
            MMA_F16(o[2][0], o[2][1], o[2][2], o[2][3], p0, p1, p2, p3, v0, v1);
            MMA_F16(o[3][0], o[3][1], o[3][2], o[3][3], p0, p1, p2, p3, v2, v3);
        }
        __syncthreads();   // all warps done with buf before next cp.async reuses it
    }

    sA += __shfl_xor_sync(0xFFFFFFFFu, sA, 1);
    sA += __shfl_xor_sync(0xFFFFFFFFu, sA, 2);
    sB += __shfl_xor_sync(0xFFFFFFFFu, sB, 1);
    sB += __shfl_xor_sync(0xFFFFFFFFu, sB, 2);
    const float invA = 1.0f / sA;
    const float invB = 1.0f / sB;

    const int r0 = q0 + (lane >> 2);
    const int r1 = r0 + 8;
    const int d0 = 2 * (lane & 3);
    float* outA = g_att + (((size_t)b * NN + r0) * HH + h) * DHH;
    float* outB = g_att + (((size_t)b * NN + r1) * HH + h) * DHH;
    #pragma unroll
    for (int nb = 0; nb < 4; nb++) {
        *(float2*)(outA + nb * 8 + d0) = make_float2(o[nb][0] * invA, o[nb][1] * invA);
        *(float2*)(outB + nb * 8 + d0) = make_float2(o[nb][2] * invB, o[nb][3] * invB);
    }
}

// ============================================================================
// Output projection: out = att @ Wo^T + bo. Plain fp16 A (no split),
// tile 32x128, grid (128, 2) = 256 CTAs, 8 warps (2m x 4n), warp 16x32.
// ============================================================================
__global__ void __launch_bounds__(256) oprojh_kernel(
        const float* __restrict__ Wo, const float* __restrict__ bo,
        float* __restrict__ out)
{
    __shared__ __align__(16) __half sA[32 * 72];    //  4608 B
    __shared__ __align__(16) __half sW[128 * 72];   // 18432 B

    const int tid = threadIdx.x, w = tid >> 5, lane = tid & 31;
    const int wm = w & 1, wn = w >> 1;
    const int m0 = blockIdx.x * 32, n0 = blockIdx.y * 128;

    float c[4][4];
    #pragma unroll
    for (int i = 0; i < 4; i++)
        #pragma unroll
        for (int j = 0; j < 4; j++) c[i][j] = 0.0f;

    const uint32_t sAB = smem_u32(sA), sWB = smem_u32(sW);
    const uint32_t aoff = (uint32_t)(wm * 16 + (lane & 7) + ((lane >> 3) & 1) * 8) * 144
                        + ((lane >> 4) & 1) * 16;
    const uint32_t wBase = (uint32_t)(wn * 32 + (lane & 7)) * 144 + ((lane >> 3) & 3) * 16;

    for (int chunk = 0; chunk < 4; chunk++) {
        const int k0 = chunk * 64;
        __syncthreads();
        {   // stage A: 32 rows x 64 cols fp32 -> fp16
            int r = tid >> 3, cg = (tid & 7) * 8;
            const float4* asrc = (const float4*)&g_att[(size_t)(m0 + r) * DIN + k0 + cg];
            #pragma unroll
            for (int j = 0; j < 2; j++) {
                float4 v = asrc[j];
                *(__half2*)&sA[r*72 + cg + 4*j]     = __halves2half2(__float2half(v.x), __float2half(v.y));
                *(__half2*)&sA[r*72 + cg + 4*j + 2] = __halves2half2(__float2half(v.z), __float2half(v.w));
            }
            // stage W: 128 rows x 64 cols fp32 -> fp16
            int r2 = tid >> 1, cg2 = (tid & 1) * 32;
            const float4* wsrc = (const float4*)&Wo[(size_t)(n0 + r2) * DIN + k0 + cg2];
            #pragma unroll
            for (int j = 0; j < 8; j++) {
                float4 v = wsrc[j];
                *(__half2*)&sW[r2*72 + cg2 + 4*j]     = __halves2half2(__float2half(v.x), __float2half(v.y));
                *(__half2*)&sW[r2*72 + cg2 + 4*j + 2] = __halves2half2(__float2half(v.z), __float2half(v.w));
            }
        }
        __syncthreads();

        uint32_t a0[4], a1[4], a2[4], a3[4];
        LDMX4(a0[0], a0[1], a0[2], a0[3], sAB + aoff);        // k 0-15
        LDMX4(a1[0], a1[1], a1[2], a1[3], sAB + aoff + 32);   // k 16-31
        LDMX4(a2[0], a2[1], a2[2], a2[3], sAB + aoff + 64);   // k 32-47
        LDMX4(a3[0], a3[1], a3[2], a3[3], sAB + aoff + 96);   // k 48-63
        #pragma unroll
        for (int nb = 0; nb < 4; nb++) {
            uint32_t b0, b1, b2, b3, b4, b5, b6, b7;
            LDMX4(b0, b1, b2, b3, sWB + wBase + nb * 1152);        // k 0-31
            LDMX4(b4, b5, b6, b7, sWB + wBase + nb * 1152 + 64);   // k 32-63
            MMA_F16(c[nb][0], c[nb][1], c[nb][2], c[nb][3],
                    a0[0], a0[1], a0[2], a0[3], b0, b1);
            MMA_F16(c[nb][0], c[nb][1], c[nb][2], c[nb][3],
                    a1[0], a1[1], a1[2], a1[3], b2, b3);
            MMA_F16(c[nb][0], c[nb][1], c[nb][2], c[nb][3],
                    a2[0], a2[1], a2[2], a2[3], b4, b5);
            MMA_F16(c[nb][0], c[nb][1], c[nb][2], c[nb][3],
                    a3[0], a3[1], a3[2], a3[3], b6, b7);
        }
    }

    const int mrow = m0 + wm * 16 + (lane >> 2);
    #pragma unroll
    for (int nb = 0; nb < 4; nb++) {
        const int o = n0 + wn * 32 + nb * 8 + 2 * (lane & 3);
        const float2 bias = *(const float2*)&bo[o];
        *(float2*)&out[(size_t)mrow * 256 + o] =
            make_float2(c[nb][0] + bias.x, c[nb][1] + bias.y);
        *(float2*)&out[(size_t)(mrow + 8) * 256 + o] =
            make_float2(c[nb][2] + bias.x, c[nb][3] + bias.y);
    }
}

// ---------------- launch ---------------------------------------------------
extern "C" void kernel_launch(void* const* d_in, const int* in_sizes, int n_in,
                              void* d_out, int out_size)
{
    const float* x   = (const float*)d_in[0];
    const float* adj = (const float*)d_in[1];
    const float* Wq  = (const float*)d_in[2];
    const float* Wk  = (const float*)d_in[3];
    const float* Wv  = (const float*)d_in[4];
    const float* Wo  = (const float*)d_in[5];
    const float* bo  = (const float*)d_in[6];
    float* out = (float*)d_out;

    qkvh_kernel<<<dim3(MROWS / 64, 2, 3), 256>>>(x, Wq, Wk, Wv);
    mask_kernel<<<(BB * NN * 64) / 256, 256>>>(adj);
    attn_kernel<<<BH * NTILE, 256>>>();
    oprojh_kernel<<<dim3(MROWS / 32, 2), 256>>>(Wo, bo, out);
}

// round 12
// speedup vs baseline: 1.4247x; 1.4247x over previous
#include <cuda_runtime.h>
#include <cuda_fp16.h>
#include <math.h>
#include <stdint.h>

// Problem constants (GraphAttentionLayer: B=2, N=2048, D_IN=256, H=8, DH=32)
#define BB   2
#define NN   2048
#define DIN  256
#define HH   8
#define DHH  32
#define MROWS (BB*NN)   // 4096
#define BH    (BB*HH)   // 16
#define KT    128       // keys per tile
#define NTILE (NN/KT)   // 16

// ---------------- scratch (device globals; no allocation allowed) ----------
__device__ uint4 g_att[(size_t)MROWS*256*2/16];   // fp16 att, (b,n,h,d) rows of 256
__device__ uint4 g_Xh [(size_t)MROWS*DIN*2/16];   // fp16 X hi
__device__ uint4 g_Xl [(size_t)MROWS*DIN*2/16];   // fp16 X lo (residual)
__device__ uint4 g_Wh [(size_t)4*DIN*DIN*2/16];   // fp16 {Wq,Wk,Wv,Wo}
__device__ uint4 g_Qb [(size_t)BH*NN*DHH/8];      // fp16 Q (scaled by log2e/sqrt(dh))
__device__ uint4 g_Kb [(size_t)BH*NN*DHH/8];      // fp16 K
__device__ uint4 g_Vt [(size_t)BH*DHH*NN/8];      // fp16 V^T (d, n)
__device__ uint4 g_mask[(size_t)BB*NN*16];        // adjacency bitmask

// ---------------- helpers ---------------------------------------------------
static __device__ __forceinline__ uint32_t smem_u32(const void* p){
    uint32_t a;
    asm("{ .reg .u64 t; cvta.to.shared.u64 t, %1; cvt.u32.u64 %0, t; }" : "=r"(a) : "l"(p));
    return a;
}
#define LDMX4(r0,r1,r2,r3,addr) \
    asm volatile("ldmatrix.sync.aligned.m8n8.x4.shared.b16 {%0,%1,%2,%3}, [%4];" \
        : "=r"(r0),"=r"(r1),"=r"(r2),"=r"(r3) : "r"(addr))
#define MMA_F16(c0,c1,c2,c3,a0,a1,a2,a3,b0,b1) \
    asm volatile("mma.sync.aligned.m16n8k16.row.col.f32.f16.f16.f32 " \
        "{%0,%1,%2,%3}, {%4,%5,%6,%7}, {%8,%9}, {%0,%1,%2,%3};" \
        : "+f"(c0),"+f"(c1),"+f"(c2),"+f"(c3) \
        : "r"(a0),"r"(a1),"r"(a2),"r"(a3), "r"(b0),"r"(b1))
static __device__ __forceinline__ uint32_t f16x2_of(float hi, float lo){
    uint32_t r;
    asm("cvt.rn.satfinite.f16x2.f32 %0, %1, %2;" : "=r"(r) : "f"(hi), "f"(lo));
    return r;
}
static __device__ __forceinline__ float ex2(float x){
    float r;
    asm("ex2.approx.ftz.f32 %0, %1;" : "=f"(r) : "f"(x));
    return r;
}
#define CP16(dst, src) \
    asm volatile("cp.async.cg.shared.global [%0], [%1], 16;" :: "r"(dst), "l"(src) : "memory")
#define CP_COMMIT() asm volatile("cp.async.commit_group;" ::: "memory")
#define CP_WAIT0()  asm volatile("cp.async.wait_group 0;" ::: "memory")

// ---------------- prep: fp32 -> fp16 images of X (split) and all W ---------
// grid 1024, block 256: one float4 of X per thread; first 65536 also do W.
__global__ void __launch_bounds__(256) prep_kernel(
        const float* __restrict__ x,  const float* __restrict__ Wq,
        const float* __restrict__ Wk, const float* __restrict__ Wv,
        const float* __restrict__ Wo)
{
    const int idx = blockIdx.x * 256 + threadIdx.x;   // [0, 262144)
    {
        float4 v = ((const float4*)x)[idx];
        __half hx = __float2half(v.x), hy = __float2half(v.y);
        __half hz = __float2half(v.z), hw = __float2half(v.w);
        __half2* Xh2 = (__half2*)g_Xh;
        __half2* Xl2 = (__half2*)g_Xl;
        Xh2[idx*2]   = __halves2half2(hx, hy);
        Xh2[idx*2+1] = __halves2half2(hz, hw);
        Xl2[idx*2]   = __halves2half2(__float2half(v.x - __half2float(hx)),
                                      __float2half(v.y - __half2float(hy)));
        Xl2[idx*2+1] = __halves2half2(__float2half(v.z - __half2float(hz)),
                                      __float2half(v.w - __half2float(hw)));
    }
    if (idx < 65536) {
        int wsel = idx >> 14, i = idx & 16383;
        const float* Ws = (wsel == 0) ? Wq : (wsel == 1) ? Wk : (wsel == 2) ? Wv : Wo;
        float4 v = ((const float4*)Ws)[i];
        __half2* Wh2 = (__half2*)g_Wh;
        Wh2[(wsel*16384 + i)*2]     = __halves2half2(__float2half(v.x), __float2half(v.y));
        Wh2[(wsel*16384 + i)*2 + 1] = __halves2half2(__float2half(v.z), __float2half(v.w));
    }
}

// ============================================================================
// QKV projection: split-fp16 A (Xh+Xl) x fp16 W, cp.async double-buffered.
// grid (64, 2, 3), block 256, tile 64m x 128n, K chunks of 32.
// ============================================================================
__global__ void __launch_bounds__(256) qkvh_kernel()
{
    __shared__ __align__(16) __half sXh[2][64 * 40];
    __shared__ __align__(16) __half sXl[2][64 * 40];
    __shared__ __align__(16) __half sW [2][128 * 40];

    const int tid = threadIdx.x, w = tid >> 5, lane = tid & 31;
    const int wm = w >> 1, wn = w & 1;
    const int m0 = blockIdx.x * 64, n0 = blockIdx.y * 128, z = blockIdx.z;

    const char* Xh = (const char*)g_Xh;                       // 512B rows
    const char* Xl = (const char*)g_Xl;
    const char* Wz = (const char*)g_Wh + (size_t)z * 131072;  // 512B rows

    const uint32_t xhB[2] = { smem_u32(sXh[0]), smem_u32(sXh[1]) };
    const uint32_t xlB[2] = { smem_u32(sXl[0]), smem_u32(sXl[1]) };
    const uint32_t wB [2] = { smem_u32(sW[0]),  smem_u32(sW[1])  };

    auto stage = [&](int c, int buf) {
        const int kb = c * 64;                 // 32 halves = 64B
        int r = tid >> 2, off = (tid & 3) * 16;
        CP16(xhB[buf] + r * 80 + off, Xh + (size_t)(m0 + r) * 512 + kb + off);
        CP16(xlB[buf] + r * 80 + off, Xl + (size_t)(m0 + r) * 512 + kb + off);
        int r2 = tid >> 1, off2 = (tid & 1) * 32;
        CP16(wB[buf] + r2 * 80 + off2,      Wz + (size_t)(n0 + r2) * 512 + kb + off2);
        CP16(wB[buf] + r2 * 80 + off2 + 16, Wz + (size_t)(n0 + r2) * 512 + kb + off2 + 16);
        CP_COMMIT();
    };

    float c[8][4];
    #pragma unroll
    for (int i = 0; i < 8; i++)
        #pragma unroll
        for (int j = 0; j < 4; j++) c[i][j] = 0.0f;

    const uint32_t aoff = (uint32_t)(wm * 16 + (lane & 7) + ((lane >> 3) & 1) * 8) * 80
                        + ((lane >> 4) & 1) * 16;
    const uint32_t boff = (uint32_t)(wn * 64 + (lane & 7)) * 80 + ((lane >> 3) & 3) * 16;

    stage(0, 0);
    for (int ch = 0; ch < 8; ch++) {
        const int buf = ch & 1;
        CP_WAIT0();
        __syncthreads();
        if (ch < 7) stage(ch + 1, buf ^ 1);

        uint32_t ah0[4], ah1[4], al0[4], al1[4];
        LDMX4(ah0[0], ah0[1], ah0[2], ah0[3], xhB[buf] + aoff);
        LDMX4(ah1[0], ah1[1], ah1[2], ah1[3], xhB[buf] + aoff + 32);
        LDMX4(al0[0], al0[1], al0[2], al0[3], xlB[buf] + aoff);
        LDMX4(al1[0], al1[1], al1[2], al1[3], xlB[buf] + aoff + 32);
        #pragma unroll
        for (int nt = 0; nt < 8; nt++) {
            uint32_t b0, b1, b2, b3;
            LDMX4(b0, b1, b2, b3, wB[buf] + boff + nt * 640);
            MMA_F16(c[nt][0], c[nt][1], c[nt][2], c[nt][3],
                    ah0[0], ah0[1], ah0[2], ah0[3], b0, b1);
            MMA_F16(c[nt][0], c[nt][1], c[nt][2], c[nt][3],
                    ah1[0], ah1[1], ah1[2], ah1[3], b2, b3);
            MMA_F16(c[nt][0], c[nt][1], c[nt][2], c[nt][3],
                    al0[0], al0[1], al0[2], al0[3], b0, b1);
            MMA_F16(c[nt][0], c[nt][1], c[nt][2], c[nt][3],
                    al1[0], al1[1], al1[2], al1[3], b2, b3);
        }
        __syncthreads();
    }

    // Q pre-scale folds log2(e) so attention uses ex2 directly.
    const float scale = (z == 0) ? 0.2550512985f : 1.0f;  // log2e/sqrt(32)
    const int mrow = m0 + wm * 16 + (lane >> 2);
    const int b = mrow >> 11, n = mrow & (NN - 1);
    __half* Vt = (__half*)g_Vt;
    __half2* QK2 = (z == 0) ? (__half2*)g_Qb : (__half2*)g_Kb;

    #pragma unroll
    for (int nt = 0; nt < 8; nt++) {
        const int o = n0 + wn * 64 + nt * 8 + 2 * (lane & 3);
        const int h = o >> 5, d = o & 31, bh = b * HH + h;
        if (z < 2) {
            QK2[(((size_t)bh * NN + n) * DHH + d) >> 1] =
                __halves2half2(__float2half(c[nt][0] * scale), __float2half(c[nt][1] * scale));
            QK2[(((size_t)bh * NN + n + 8) * DHH + d) >> 1] =
                __halves2half2(__float2half(c[nt][2] * scale), __float2half(c[nt][3] * scale));
        } else {
            Vt[((size_t)bh * DHH + d)     * NN + n]     = __float2half(c[nt][0]);
            Vt[((size_t)bh * DHH + d + 1) * NN + n]     = __float2half(c[nt][1]);
            Vt[((size_t)bh * DHH + d)     * NN + n + 8] = __float2half(c[nt][2]);
            Vt[((size_t)bh * DHH + d + 1) * NN + n + 8] = __float2half(c[nt][3]);
        }
    }
}

// ---------------- mask: adjacency -> bitmask -------------------------------
__global__ void __launch_bounds__(256) mask_kernel(const float* __restrict__ adj)
{
    int idx = blockIdx.x * 256 + threadIdx.x;
    int b = idx >> 17, rem = idx & 131071, n = rem >> 6, w = rem & 63;
    const float4* a4 = (const float4*)(adj + ((size_t)b * NN + n) * NN + w * 32);
    uint32_t m = 0;
    #pragma unroll
    for (int i = 0; i < 8; i++) {
        float4 v = a4[i];
        m |= (v.x != 0.0f ? 1u : 0u) << (i * 4 + 0);
        m |= (v.y != 0.0f ? 1u : 0u) << (i * 4 + 1);
        m |= (v.z != 0.0f ? 1u : 0u) << (i * 4 + 2);
        m |= (v.w != 0.0f ? 1u : 0u) << (i * 4 + 3);
    }
    ((uint32_t*)g_mask)[idx] = m;
}

// ============================================================================
// HMMA flash attention: fp16 operands, fp32 accum, MUFU ex2 softmax,
// cp.async double-buffered K/V/mask staging. fp16 output.
// grid 256, block 256 (8 warps x 16 query rows).
// ============================================================================
__global__ void __launch_bounds__(256, 2) attn_kernel()
{
    __shared__ __align__(16) __half sK[2][128 * 40];
    __shared__ __align__(16) __half sVt[2][32 * 136];
    __shared__ __align__(16) uint4 sMask[2][8][16];

    const int tid  = threadIdx.x;
    const int w    = tid >> 5;
    const int lane = tid & 31;
    const int bh   = blockIdx.x >> 4, qt = blockIdx.x & 15;
    const int b    = bh >> 3, h = bh & 7;
    const int q0   = qt * 128 + w * 16;

    const uint32_t kBufB[2] = { smem_u32(sK[0]),    smem_u32(sK[1]) };
    const uint32_t vBufB[2] = { smem_u32(sVt[0]),   smem_u32(sVt[1]) };
    const uint32_t mBufB[2] = { smem_u32(sMask[0]), smem_u32(sMask[1]) };

    {
        const uint4* src = g_Qb + ((size_t)bh * NN + qt * 128) * 4;
        int r = tid >> 1, hf = tid & 1;
        uint4* dst = (uint4*)(sK[0] + r * 40) + hf * 2;
        dst[0] = src[r * 4 + hf * 2];
        dst[1] = src[r * 4 + hf * 2 + 1];
    }
    __syncthreads();

    uint32_t aq[2][4];
    {
        const int arow = (lane & 7) + ((lane >> 3) & 1) * 8 + w * 16;
        const uint32_t kb = ((lane >> 4) & 1) * 16;
        uint32_t a0 = kBufB[0] + arow * 80 + kb;
        LDMX4(aq[0][0], aq[0][1], aq[0][2], aq[0][3], a0);
        LDMX4(aq[1][0], aq[1][1], aq[1][2], aq[1][3], a0 + 32);
    }
    __syncthreads();

    const uint32_t kLane = (lane & 7) * 80 + ((lane >> 3) & 3) * 16;
    const uint32_t vLane = ((lane & 7) + ((lane >> 4) & 1) * 8) * 272
                         + ((lane >> 3) & 1) * 16;

    auto stage = [&](int t, int buf) {
        const char* ksrc = (const char*)(g_Kb + ((size_t)bh * NN + t * 128) * 4);
        int r = tid >> 1, hf = tid & 1;
        uint32_t kdst = kBufB[buf] + r * 80 + hf * 32;
        CP16(kdst,      ksrc + r * 64 + hf * 32);
        CP16(kdst + 16, ksrc + r * 64 + hf * 32 + 16);
        const char* vsrc = (const char*)(g_Vt + (size_t)bh * DHH * (NN / 8) + (size_t)t * 16);
        int vr = tid >> 3, oct = tid & 7;
        uint32_t vdst = vBufB[buf] + vr * 272 + oct * 32;
        CP16(vdst,      vsrc + vr * (NN * 2) + oct * 32);
        CP16(vdst + 16, vsrc + vr * (NN * 2) + oct * 32 + 16);
        if (tid < 128) {
            int ww = tid >> 4, l = tid & 15;
            const char* msrc = (const char*)(g_mask + ((size_t)b * NN + qt * 128 + ww * 16 + l) * 16 + t);
            CP16(mBufB[buf] + (ww * 16 + l) * 16, msrc);
        }
        CP_COMMIT();
    };

    stage(0, 0);

    float o[4][4];
    #pragma unroll
    for (int i = 0; i < 4; i++)
        #pragma unroll
        for (int j = 0; j < 4; j++) o[i][j] = 0.0f;
    float sA = 0.0f, sB = 0.0f;

    for (int t = 0; t < NTILE; t++) {
        const int buf = t & 1;
        CP_WAIT0();
        __syncthreads();
        if (t < NTILE - 1) stage(t + 1, buf ^ 1);

        const uint32_t kBase = kBufB[buf] + kLane;
        const uint32_t vBase = vBufB[buf] + vLane;
        uint4 mA = sMask[buf][w][lane >> 2];
        uint4 mB = sMask[buf][w][8 + (lane >> 2)];

        float c[16][4];
        #pragma unroll
        for (int nb = 0; nb < 16; nb++) {
            c[nb][0] = c[nb][1] = c[nb][2] = c[nb][3] = 0.0f;
            uint32_t b0, b1, b2, b3;
            LDMX4(b0, b1, b2, b3, kBase + nb * 640);
            MMA_F16(c[nb][0], c[nb][1], c[nb][2], c[nb][3],
                    aq[0][0], aq[0][1], aq[0][2], aq[0][3], b0, b1);
            MMA_F16(c[nb][0], c[nb][1], c[nb][2], c[nb][3],
                    aq[1][0], aq[1][1], aq[1][2], aq[1][3], b2, b3);
        }

        const int bshift = 2 * (lane & 3);
        #pragma unroll
        for (int nb = 0; nb < 16; nb++) {
            uint32_t wA = (nb < 4) ? mA.x : (nb < 8) ? mA.y : (nb < 12) ? mA.z : mA.w;
            uint32_t wB = (nb < 4) ? mB.x : (nb < 8) ? mB.y : (nb < 12) ? mB.z : mB.w;
            int s0 = (nb & 3) * 8 + bshift;
            float p0 = ((wA >> s0) & 1u)     ? ex2(c[nb][0]) : 0.0f;
            float p1 = ((wA >> (s0+1)) & 1u) ? ex2(c[nb][1]) : 0.0f;
            float p2 = ((wB >> s0) & 1u)     ? ex2(c[nb][2]) : 0.0f;
            float p3 = ((wB >> (s0+1)) & 1u) ? ex2(c[nb][3]) : 0.0f;
            c[nb][0] = p0; c[nb][1] = p1; c[nb][2] = p2; c[nb][3] = p3;
            sA += p0 + p1;
            sB += p2 + p3;
        }

        #pragma unroll
        for (int j = 0; j < 8; j++) {
            uint32_t p0 = f16x2_of(c[2*j][1],   c[2*j][0]);
            uint32_t p1 = f16x2_of(c[2*j][3],   c[2*j][2]);
            uint32_t p2 = f16x2_of(c[2*j+1][1], c[2*j+1][0]);
            uint32_t p3 = f16x2_of(c[2*j+1][3], c[2*j+1][2]);
            uint32_t v0, v1, v2, v3;
            LDMX4(v0, v1, v2, v3, vBase + j * 32);
            MMA_F16(o[0][0], o[0][1], o[0][2], o[0][3], p0, p1, p2, p3, v0, v1);
            MMA_F16(o[1][0], o[1][1], o[1][2], o[1][3], p0, p1, p2, p3, v2, v3);
            LDMX4(v0, v1, v2, v3, vBase + 16 * 272 + j * 32);
            MMA_F16(o[2][0], o[2][1], o[2][2], o[2][3], p0, p1, p2, p3, v0, v1);
            MMA_F16(o[3][0], o[3][1], o[3][2], o[3][3], p0, p1, p2, p3, v2, v3);
        }
        __syncthreads();
    }

    sA += __shfl_xor_sync(0xFFFFFFFFu, sA, 1);
    sA += __shfl_xor_sync(0xFFFFFFFFu, sA, 2);
    sB += __shfl_xor_sync(0xFFFFFFFFu, sB, 1);
    sB += __shfl_xor_sync(0xFFFFFFFFu, sB, 2);
    const float invA = 1.0f / sA;
    const float invB = 1.0f / sB;

    const int r0 = q0 + (lane >> 2);
    const int r1 = r0 + 8;
    const int d0 = 2 * (lane & 3);
    __half* attp = (__half*)g_att;
    const size_t baseA = (((size_t)b * NN + r0) * HH + h) * DHH;
    const size_t baseB = (((size_t)b * NN + r1) * HH + h) * DHH;
    #pragma unroll
    for (int nb = 0; nb < 4; nb++) {
        *(__half2*)&attp[baseA + nb * 8 + d0] =
            __halves2half2(__float2half(o[nb][0] * invA), __float2half(o[nb][1] * invA));
        *(__half2*)&attp[baseB + nb * 8 + d0] =
            __halves2half2(__float2half(o[nb][2] * invB), __float2half(o[nb][3] * invB));
    }
}

// ============================================================================
// Output projection: out = att(fp16) @ Wo(fp16)^T + bo, cp.async pipelined.
// grid (64, 2), block 256, tile 64m x 128n, K chunks of 32.
// ============================================================================
__global__ void __launch_bounds__(256) oprojh_kernel(
        const float* __restrict__ bo, float* __restrict__ out)
{
    __shared__ __align__(16) __half sA[2][64 * 40];
    __shared__ __align__(16) __half sW[2][128 * 40];

    const int tid = threadIdx.x, w = tid >> 5, lane = tid & 31;
    const int wm = w >> 1, wn = w & 1;
    const int m0 = blockIdx.x * 64, n0 = blockIdx.y * 128;

    const char* A  = (const char*)g_att;                      // 512B rows
    const char* Wz = (const char*)g_Wh + (size_t)3 * 131072;  // Wo

    const uint32_t aB[2] = { smem_u32(sA[0]), smem_u32(sA[1]) };
    const uint32_t wB[2] = { smem_u32(sW[0]), smem_u32(sW[1]) };

    auto stage = [&](int c, int buf) {
        const int kb = c * 64;
        int r = tid >> 2, off = (tid & 3) * 16;
        CP16(aB[buf] + r * 80 + off, A + (size_t)(m0 + r) * 512 + kb + off);
        int r2 = tid >> 1, off2 = (tid & 1) * 32;
        CP16(wB[buf] + r2 * 80 + off2,      Wz + (size_t)(n0 + r2) * 512 + kb + off2);
        CP16(wB[buf] + r2 * 80 + off2 + 16, Wz + (size_t)(n0 + r2) * 512 + kb + off2 + 16);
        CP_COMMIT();
    };

    float c[8][4];
    #pragma unroll
    for (int i = 0; i < 8; i++)
        #pragma unroll
        for (int j = 0; j < 4; j++) c[i][j] = 0.0f;

    const uint32_t aoff = (uint32_t)(wm * 16 + (lane & 7) + ((lane >> 3) & 1) * 8) * 80
                        + ((lane >> 4) & 1) * 16;
    const uint32_t boff = (uint32_t)(wn * 64 + (lane & 7)) * 80 + ((lane >> 3) & 3) * 16;

    stage(0, 0);
    for (int ch = 0; ch < 8; ch++) {
        const int buf = ch & 1;
        CP_WAIT0();
        __syncthreads();
        if (ch < 7) stage(ch + 1, buf ^ 1);

        uint32_t a0[4], a1[4];
        LDMX4(a0[0], a0[1], a0[2], a0[3], aB[buf] + aoff);
        LDMX4(a1[0], a1[1], a1[2], a1[3], aB[buf] + aoff + 32);
        #pragma unroll
        for (int nt = 0; nt < 8; nt++) {
            uint32_t b0, b1, b2, b3;
            LDMX4(b0, b1, b2, b3, wB[buf] + boff + nt * 640);
            MMA_F16(c[nt][0], c[nt][1], c[nt][2], c[nt][3],
                    a0[0], a0[1], a0[2], a0[3], b0, b1);
            MMA_F16(c[nt][0], c[nt][1], c[nt][2], c[nt][3],
                    a1[0], a1[1], a1[2], a1[3], b2, b3);
        }
        __syncthreads();
    }

    const int mrow = m0 + wm * 16 + (lane >> 2);
    #pragma unroll
    for (int nt = 0; nt < 8; nt++) {
        const int o = n0 + wn * 64 + nt * 8 + 2 * (lane & 3);
        const float2 bias = *(const float2*)&bo[o];
        *(float2*)&out[(size_t)mrow * 256 + o] =
            make_float2(c[nt][0] + bias.x, c[nt][1] + bias.y);
        *(float2*)&out[(size_t)(mrow + 8) * 256 + o] =
            make_float2(c[nt][2] + bias.x, c[nt][3] + bias.y);
    }
}

// ---------------- launch ---------------------------------------------------
extern "C" void kernel_launch(void* const* d_in, const int* in_sizes, int n_in,
                              void* d_out, int out_size)
{
    const float* x   = (const float*)d_in[0];
    const float* adj = (const float*)d_in[1];
    const float* Wq  = (const float*)d_in[2];
    const float* Wk  = (const float*)d_in[3];
    const float* Wv  = (const float*)d_in[4];
    const float* Wo  = (const float*)d_in[5];
    const float* bo  = (const float*)d_in[6];
    float* out = (float*)d_out;

    prep_kernel<<<1024, 256>>>(x, Wq, Wk, Wv, Wo);
    qkvh_kernel<<<dim3(MROWS / 64, 2, 3), 256>>>();
    mask_kernel<<<(BB * NN * 64) / 256, 256>>>(adj);
    attn_kernel<<<BH * NTILE, 256>>>();
    oprojh_kernel<<<dim3(MROWS / 64, 2), 256>>>(bo, out);
}

// round 13
// speedup vs baseline: 1.5194x; 1.0664x over previous
#include <cuda_runtime.h>
#include <cuda_fp16.h>
#include <math.h>
#include <stdint.h>

// Problem constants (GraphAttentionLayer: B=2, N=2048, D_IN=256, H=8, DH=32)
#define BB   2
#define NN   2048
#define DIN  256
#define HH   8
#define DHH  32
#define MROWS (BB*NN)   // 4096
#define BH    (BB*HH)   // 16
#define KT    128       // keys per tile
#define NTILE (NN/KT)   // 16

// ---------------- scratch (device globals; no allocation allowed) ----------
__device__ uint4 g_att[(size_t)MROWS*256*2/16];   // fp16 att, (b,n,h,d) rows of 256
__device__ uint4 g_Xh [(size_t)MROWS*DIN*2/16];   // fp16 X hi
__device__ uint4 g_Xl [(size_t)MROWS*DIN*2/16];   // fp16 X lo (residual)
__device__ uint4 g_Wh [(size_t)4*DIN*DIN*2/16];   // fp16 {Wq,Wk,Wv,Wo}
__device__ uint4 g_Qb [(size_t)BH*NN*DHH/8];      // fp16 Q (scaled by log2e/sqrt(dh))
__device__ uint4 g_Kb [(size_t)BH*NN*DHH/8];      // fp16 K
__device__ uint4 g_Vt [(size_t)BH*DHH*NN/8];      // fp16 V^T (d, n)
__device__ uint4 g_mask[(size_t)BB*NN*16];        // adjacency bitmask

// ---------------- helpers ---------------------------------------------------
static __device__ __forceinline__ uint32_t smem_u32(const void* p){
    uint32_t a;
    asm("{ .reg .u64 t; cvta.to.shared.u64 t, %1; cvt.u32.u64 %0, t; }" : "=r"(a) : "l"(p));
    return a;
}
#define LDMX4(r0,r1,r2,r3,addr) \
    asm volatile("ldmatrix.sync.aligned.m8n8.x4.shared.b16 {%0,%1,%2,%3}, [%4];" \
        : "=r"(r0),"=r"(r1),"=r"(r2),"=r"(r3) : "r"(addr))
#define MMA_F16(c0,c1,c2,c3,a0,a1,a2,a3,b0,b1) \
    asm volatile("mma.sync.aligned.m16n8k16.row.col.f32.f16.f16.f32 " \
        "{%0,%1,%2,%3}, {%4,%5,%6,%7}, {%8,%9}, {%0,%1,%2,%3};" \
        : "+f"(c0),"+f"(c1),"+f"(c2),"+f"(c3) \
        : "r"(a0),"r"(a1),"r"(a2),"r"(a3), "r"(b0),"r"(b1))
static __device__ __forceinline__ uint32_t f16x2_of(float hi, float lo){
    uint32_t r;
    asm("cvt.rn.satfinite.f16x2.f32 %0, %1, %2;" : "=r"(r) : "f"(hi), "f"(lo));
    return r;
}
static __device__ __forceinline__ float ex2(float x){
    float r;
    asm("ex2.approx.ftz.f32 %0, %1;" : "=f"(r) : "f"(x));
    return r;
}
#define CP16(dst, src) \
    asm volatile("cp.async.cg.shared.global [%0], [%1], 16;" :: "r"(dst), "l"(src) : "memory")
#define CP_COMMIT() asm volatile("cp.async.commit_group;" ::: "memory")
#define CP_WAIT0()  asm volatile("cp.async.wait_group 0;" ::: "memory")

// ---------------- prep: X->(Xh,Xl), W->fp16, adj->bitmask (merged) ---------
// grid 1024, block 256: idx in [0, 262144).
__global__ void __launch_bounds__(256) prep_kernel(
        const float* __restrict__ x,  const float* __restrict__ Wq,
        const float* __restrict__ Wk, const float* __restrict__ Wv,
        const float* __restrict__ Wo, const float* __restrict__ adj)
{
    const int idx = blockIdx.x * 256 + threadIdx.x;   // [0, 262144)
    {
        float4 v = ((const float4*)x)[idx];
        __half hx = __float2half(v.x), hy = __float2half(v.y);
        __half hz = __float2half(v.z), hw = __float2half(v.w);
        __half2* Xh2 = (__half2*)g_Xh;
        __half2* Xl2 = (__half2*)g_Xl;
        Xh2[idx*2]   = __halves2half2(hx, hy);
        Xh2[idx*2+1] = __halves2half2(hz, hw);
        Xl2[idx*2]   = __halves2half2(__float2half(v.x - __half2float(hx)),
                                      __float2half(v.y - __half2float(hy)));
        Xl2[idx*2+1] = __halves2half2(__float2half(v.z - __half2float(hz)),
                                      __float2half(v.w - __half2float(hw)));
    }
    if (idx < 65536) {
        int wsel = idx >> 14, i = idx & 16383;
        const float* Ws = (wsel == 0) ? Wq : (wsel == 1) ? Wk : (wsel == 2) ? Wv : Wo;
        float4 v = ((const float4*)Ws)[i];
        __half2* Wh2 = (__half2*)g_Wh;
        Wh2[(wsel*16384 + i)*2]     = __halves2half2(__float2half(v.x), __float2half(v.y));
        Wh2[(wsel*16384 + i)*2 + 1] = __halves2half2(__float2half(v.z), __float2half(v.w));
    }
    {   // adjacency bitmask: idx over BB*NN*64 words (= 262144 exactly)
        int b = idx >> 17, rem = idx & 131071, n = rem >> 6, w = rem & 63;
        const float4* a4 = (const float4*)(adj + ((size_t)b * NN + n) * NN + w * 32);
        uint32_t m = 0;
        #pragma unroll
        for (int i = 0; i < 8; i++) {
            float4 v = a4[i];
            m |= (v.x != 0.0f ? 1u : 0u) << (i * 4 + 0);
            m |= (v.y != 0.0f ? 1u : 0u) << (i * 4 + 1);
            m |= (v.z != 0.0f ? 1u : 0u) << (i * 4 + 2);
            m |= (v.w != 0.0f ? 1u : 0u) << (i * 4 + 3);
        }
        ((uint32_t*)g_mask)[idx] = m;
    }
}

// ============================================================================
// QKV projection: split-fp16 A (Xh+Xl) x fp16 W, cp.async double-buffered.
// grid (64, 2, 3), block 256, tile 64m x 128n, K chunks of 32.
// ============================================================================
__global__ void __launch_bounds__(256) qkvh_kernel()
{
    __shared__ __align__(16) __half sXh[2][64 * 40];
    __shared__ __align__(16) __half sXl[2][64 * 40];
    __shared__ __align__(16) __half sW [2][128 * 40];

    const int tid = threadIdx.x, w = tid >> 5, lane = tid & 31;
    const int wm = w >> 1, wn = w & 1;
    const int m0 = blockIdx.x * 64, n0 = blockIdx.y * 128, z = blockIdx.z;

    const char* Xh = (const char*)g_Xh;                       // 512B rows
    const char* Xl = (const char*)g_Xl;
    const char* Wz = (const char*)g_Wh + (size_t)z * 131072;  // 512B rows

    const uint32_t xhB[2] = { smem_u32(sXh[0]), smem_u32(sXh[1]) };
    const uint32_t xlB[2] = { smem_u32(sXl[0]), smem_u32(sXl[1]) };
    const uint32_t wB [2] = { smem_u32(sW[0]),  smem_u32(sW[1])  };

    auto stage = [&](int c, int buf) {
        const int kb = c * 64;                 // 32 halves = 64B
        int r = tid >> 2, off = (tid & 3) * 16;
        CP16(xhB[buf] + r * 80 + off, Xh + (size_t)(m0 + r) * 512 + kb + off);
        CP16(xlB[buf] + r * 80 + off, Xl + (size_t)(m0 + r) * 512 + kb + off);
        int r2 = tid >> 1, off2 = (tid & 1) * 32;
        CP16(wB[buf] + r2 * 80 + off2,      Wz + (size_t)(n0 + r2) * 512 + kb + off2);
        CP16(wB[buf] + r2 * 80 + off2 + 16, Wz + (size_t)(n0 + r2) * 512 + kb + off2 + 16);
        CP_COMMIT();
    };

    float c[8][4];
    #pragma unroll
    for (int i = 0; i < 8; i++)
        #pragma unroll
        for (int j = 0; j < 4; j++) c[i][j] = 0.0f;

    const uint32_t aoff = (uint32_t)(wm * 16 + (lane & 7) + ((lane >> 3) & 1) * 8) * 80
                        + ((lane >> 4) & 1) * 16;
    const uint32_t boff = (uint32_t)(wn * 64 + (lane & 7)) * 80 + ((lane >> 3) & 3) * 16;

    stage(0, 0);
    for (int ch = 0; ch < 8; ch++) {
        const int buf = ch & 1;
        CP_WAIT0();
        __syncthreads();
        if (ch < 7) stage(ch + 1, buf ^ 1);

        uint32_t ah0[4], ah1[4], al0[4], al1[4];
        LDMX4(ah0[0], ah0[1], ah0[2], ah0[3], xhB[buf] + aoff);
        LDMX4(ah1[0], ah1[1], ah1[2], ah1[3], xhB[buf] + aoff + 32);
        LDMX4(al0[0], al0[1], al0[2], al0[3], xlB[buf] + aoff);
        LDMX4(al1[0], al1[1], al1[2], al1[3], xlB[buf] + aoff + 32);
        #pragma unroll
        for (int nt = 0; nt < 8; nt++) {
            uint32_t b0, b1, b2, b3;
            LDMX4(b0, b1, b2, b3, wB[buf] + boff + nt * 640);
            MMA_F16(c[nt][0], c[nt][1], c[nt][2], c[nt][3],
                    ah0[0], ah0[1], ah0[2], ah0[3], b0, b1);
            MMA_F16(c[nt][0], c[nt][1], c[nt][2], c[nt][3],
                    ah1[0], ah1[1], ah1[2], ah1[3], b2, b3);
            MMA_F16(c[nt][0], c[nt][1], c[nt][2], c[nt][3],
                    al0[0], al0[1], al0[2], al0[3], b0, b1);
            MMA_F16(c[nt][0], c[nt][1], c[nt][2], c[nt][3],
                    al1[0], al1[1], al1[2], al1[3], b2, b3);
        }
        __syncthreads();
    }

    // Q pre-scale folds log2(e) so attention uses ex2 directly.
    const float scale = (z == 0) ? 0.2550512985f : 1.0f;  // log2e/sqrt(32)
    const int mrow = m0 + wm * 16 + (lane >> 2);
    const int b = mrow >> 11, n = mrow & (NN - 1);
    __half* Vt = (__half*)g_Vt;
    __half2* QK2 = (z == 0) ? (__half2*)g_Qb : (__half2*)g_Kb;

    #pragma unroll
    for (int nt = 0; nt < 8; nt++) {
        const int o = n0 + wn * 64 + nt * 8 + 2 * (lane & 3);
        const int h = o >> 5, d = o & 31, bh = b * HH + h;
        if (z < 2) {
            QK2[(((size_t)bh * NN + n) * DHH + d) >> 1] =
                __halves2half2(__float2half(c[nt][0] * scale), __float2half(c[nt][1] * scale));
            QK2[(((size_t)bh * NN + n + 8) * DHH + d) >> 1] =
                __halves2half2(__float2half(c[nt][2] * scale), __float2half(c[nt][3] * scale));
        } else {
            Vt[((size_t)bh * DHH + d)     * NN + n]     = __float2half(c[nt][0]);
            Vt[((size_t)bh * DHH + d + 1) * NN + n]     = __float2half(c[nt][1]);
            Vt[((size_t)bh * DHH + d)     * NN + n + 8] = __float2half(c[nt][2]);
            Vt[((size_t)bh * DHH + d + 1) * NN + n + 8] = __float2half(c[nt][3]);
        }
    }
}

// ============================================================================
// HMMA flash attention: fp16 operands, fp32 accum, MUFU ex2 softmax,
// cp.async double-buffered K/V staging, direct-LDG mask, rowsum via
// ones-column MMA (denominator accumulated on the tensor pipe).
// grid 256, block 256 (8 warps x 16 query rows).
// ============================================================================
__global__ void __launch_bounds__(256, 2) attn_kernel()
{
    __shared__ __align__(16) __half sK[2][128 * 40];
    __shared__ __align__(16) __half sVt[2][32 * 136];

    const int tid  = threadIdx.x;
    const int w    = tid >> 5;
    const int lane = tid & 31;
    const int bh   = blockIdx.x >> 4, qt = blockIdx.x & 15;
    const int b    = bh >> 3, h = bh & 7;
    const int q0   = qt * 128 + w * 16;

    const uint32_t kBufB[2] = { smem_u32(sK[0]),  smem_u32(sK[1]) };
    const uint32_t vBufB[2] = { smem_u32(sVt[0]), smem_u32(sVt[1]) };

    {
        const uint4* src = g_Qb + ((size_t)bh * NN + qt * 128) * 4;
        int r = tid >> 1, hf = tid & 1;
        uint4* dst = (uint4*)(sK[0] + r * 40) + hf * 2;
        dst[0] = src[r * 4 + hf * 2];
        dst[1] = src[r * 4 + hf * 2 + 1];
    }
    __syncthreads();

    uint32_t aq[2][4];
    {
        const int arow = (lane & 7) + ((lane >> 3) & 1) * 8 + w * 16;
        const uint32_t kb = ((lane >> 4) & 1) * 16;
        uint32_t a0 = kBufB[0] + arow * 80 + kb;
        LDMX4(aq[0][0], aq[0][1], aq[0][2], aq[0][3], a0);
        LDMX4(aq[1][0], aq[1][1], aq[1][2], aq[1][3], a0 + 32);
    }
    __syncthreads();

    const uint32_t kLane = (lane & 7) * 80 + ((lane >> 3) & 3) * 16;
    const uint32_t vLane = ((lane & 7) + ((lane >> 4) & 1) * 8) * 272
                         + ((lane >> 3) & 1) * 16;

    auto stage = [&](int t, int buf) {
        const char* ksrc = (const char*)(g_Kb + ((size_t)bh * NN + t * 128) * 4);
        int r = tid >> 1, hf = tid & 1;
        uint32_t kdst = kBufB[buf] + r * 80 + hf * 32;
        CP16(kdst,      ksrc + r * 64 + hf * 32);
        CP16(kdst + 16, ksrc + r * 64 + hf * 32 + 16);
        const char* vsrc = (const char*)(g_Vt + (size_t)bh * DHH * (NN / 8) + (size_t)t * 16);
        int vr = tid >> 3, oct = tid & 7;
        uint32_t vdst = vBufB[buf] + vr * 272 + oct * 32;
        CP16(vdst,      vsrc + vr * (NN * 2) + oct * 32);
        CP16(vdst + 16, vsrc + vr * (NN * 2) + oct * 32 + 16);
        CP_COMMIT();
    };

    stage(0, 0);

    // per-thread mask row pointers (quad-broadcast LDG, L2-resident)
    const int r0 = q0 + (lane >> 2);
    const int r1 = r0 + 8;
    const uint4* mrowA = g_mask + ((size_t)b * NN + r0) * 16;
    const uint4* mrowB = g_mask + ((size_t)b * NN + r1) * 16;

    // ones-column B fragment for rowsum MMA (col n=0 all ones)
    const uint32_t bones = (lane < 4) ? 0x3C003C00u : 0u;

    float o[4][4];
    #pragma unroll
    for (int i = 0; i < 4; i++)
        #pragma unroll
        for (int j = 0; j < 4; j++) o[i][j] = 0.0f;
    float o4[4] = {0.0f, 0.0f, 0.0f, 0.0f};   // col0 accumulates rowsum

    for (int t = 0; t < NTILE; t++) {
        const int buf = t & 1;
        CP_WAIT0();
        __syncthreads();
        if (t < NTILE - 1) stage(t + 1, buf ^ 1);

        const uint32_t kBase = kBufB[buf] + kLane;
        const uint32_t vBase = vBufB[buf] + vLane;
        uint4 mA = mrowA[t];   // LDG issued here; latency hidden under QK MMAs
        uint4 mB = mrowB[t];

        float c[16][4];
        #pragma unroll
        for (int nb = 0; nb < 16; nb++) {
            c[nb][0] = c[nb][1] = c[nb][2] = c[nb][3] = 0.0f;
            uint32_t b0, b1, b2, b3;
            LDMX4(b0, b1, b2, b3, kBase + nb * 640);
            MMA_F16(c[nb][0], c[nb][1], c[nb][2], c[nb][3],
                    aq[0][0], aq[0][1], aq[0][2], aq[0][3], b0, b1);
            MMA_F16(c[nb][0], c[nb][1], c[nb][2], c[nb][3],
                    aq[1][0], aq[1][1], aq[1][2], aq[1][3], b2, b3);
        }

        // ---- mask + ex2 (no rowsum FADDs; denominator comes from MMA) ----
        const int bshift = 2 * (lane & 3);
        #pragma unroll
        for (int nb = 0; nb < 16; nb++) {
            uint32_t wA = (nb < 4) ? mA.x : (nb < 8) ? mA.y : (nb < 12) ? mA.z : mA.w;
            uint32_t wB = (nb < 4) ? mB.x : (nb < 8) ? mB.y : (nb < 12) ? mB.z : mB.w;
            int s0 = (nb & 3) * 8 + bshift;
            c[nb][0] = ((wA >> s0) & 1u)     ? ex2(c[nb][0]) : 0.0f;
            c[nb][1] = ((wA >> (s0+1)) & 1u) ? ex2(c[nb][1]) : 0.0f;
            c[nb][2] = ((wB >> s0) & 1u)     ? ex2(c[nb][2]) : 0.0f;
            c[nb][3] = ((wB >> (s0+1)) & 1u) ? ex2(c[nb][3]) : 0.0f;
        }

        // ---- P @ V^T (+ ones-column rowsum MMA) ----
        #pragma unroll
        for (int j = 0; j < 8; j++) {
            uint32_t p0 = f16x2_of(c[2*j][1],   c[2*j][0]);
            uint32_t p1 = f16x2_of(c[2*j][3],   c[2*j][2]);
            uint32_t p2 = f16x2_of(c[2*j+1][1], c[2*j+1][0]);
            uint32_t p3 = f16x2_of(c[2*j+1][3], c[2*j+1][2]);
            uint32_t v0, v1, v2, v3;
            LDMX4(v0, v1, v2, v3, vBase + j * 32);
            MMA_F16(o[0][0], o[0][1], o[0][2], o[0][3], p0, p1, p2, p3, v0, v1);
            MMA_F16(o[1][0], o[1][1], o[1][2], o[1][3], p0, p1, p2, p3, v2, v3);
            LDMX4(v0, v1, v2, v3, vBase + 16 * 272 + j * 32);
            MMA_F16(o[2][0], o[2][1], o[2][2], o[2][3], p0, p1, p2, p3, v0, v1);
            MMA_F16(o[3][0], o[3][1], o[3][2], o[3][3], p0, p1, p2, p3, v2, v3);
            MMA_F16(o4[0], o4[1], o4[2], o4[3], p0, p1, p2, p3, bones, bones);
        }
        __syncthreads();
    }

    // rowsum sits in col 0 of the o4 block (quad leader's c0 / c2)
    const float sumA = __shfl_sync(0xFFFFFFFFu, o4[0], lane & ~3);
    const float sumB = __shfl_sync(0xFFFFFFFFu, o4[2], lane & ~3);
    const float invA = 1.0f / sumA;
    const float invB = 1.0f / sumB;

    const int d0 = 2 * (lane & 3);
    __half* attp = (__half*)g_att;
    const size_t baseA = (((size_t)b * NN + r0) * HH + h) * DHH;
    const size_t baseB = (((size_t)b * NN + r1) * HH + h) * DHH;
    #pragma unroll
    for (int nb = 0; nb < 4; nb++) {
        *(__half2*)&attp[baseA + nb * 8 + d0] =
            __halves2half2(__float2half(o[nb][0] * invA), __float2half(o[nb][1] * invA));
        *(__half2*)&attp[baseB + nb * 8 + d0] =
            __halves2half2(__float2half(o[nb][2] * invB), __float2half(o[nb][3] * invB));
    }
}

// ============================================================================
// Output projection: out = att(fp16) @ Wo(fp16)^T + bo, cp.async pipelined.
// grid (64, 2), block 256, tile 64m x 128n, K chunks of 32.
// ============================================================================
__global__ void __launch_bounds__(256) oprojh_kernel(
        const float* __restrict__ bo, float* __restrict__ out)
{
    __shared__ __align__(16) __half sA[2][64 * 40];
    __shared__ __align__(16) __half sW[2][128 * 40];

    const int tid = threadIdx.x, w = tid >> 5, lane = tid & 31;
    const int wm = w >> 1, wn = w & 1;
    const int m0 = blockIdx.x * 64, n0 = blockIdx.y * 128;

    const char* A  = (const char*)g_att;                      // 512B rows
    const char* Wz = (const char*)g_Wh + (size_t)3 * 131072;  // Wo

    const uint32_t aB[2] = { smem_u32(sA[0]), smem_u32(sA[1]) };
    const uint32_t wB[2] = { smem_u32(sW[0]), smem_u32(sW[1]) };

    auto stage = [&](int c, int buf) {
        const int kb = c * 64;
        int r = tid >> 2, off = (tid & 3) * 16;
        CP16(aB[buf] + r * 80 + off, A + (size_t)(m0 + r) * 512 + kb + off);
        int r2 = tid >> 1, off2 = (tid & 1) * 32;
        CP16(wB[buf] + r2 * 80 + off2,      Wz + (size_t)(n0 + r2) * 512 + kb + off2);
        CP16(wB[buf] + r2 * 80 + off2 + 16, Wz + (size_t)(n0 + r2) * 512 + kb + off2 + 16);
        CP_COMMIT();
    };

    float c[8][4];
    #pragma unroll
    for (int i = 0; i < 8; i++)
        #pragma unroll
        for (int j = 0; j < 4; j++) c[i][j] = 0.0f;

    const uint32_t aoff = (uint32_t)(wm * 16 + (lane & 7) + ((lane >> 3) & 1) * 8) * 80
                        + ((lane >> 4) & 1) * 16;
    const uint32_t boff = (uint32_t)(wn * 64 + (lane & 7)) * 80 + ((lane >> 3) & 3) * 16;

    stage(0, 0);
    for (int ch = 0; ch < 8; ch++) {
        const int buf = ch & 1;
        CP_WAIT0();
        __syncthreads();
        if (ch < 7) stage(ch + 1, buf ^ 1);

        uint32_t a0[4], a1[4];
        LDMX4(a0[0], a0[1], a0[2], a0[3], aB[buf] + aoff);
        LDMX4(a1[0], a1[1], a1[2], a1[3], aB[buf] + aoff + 32);
        #pragma unroll
        for (int nt = 0; nt < 8; nt++) {
            uint32_t b0, b1, b2, b3;
            LDMX4(b0, b1, b2, b3, wB[buf] + boff + nt * 640);
            MMA_F16(c[nt][0], c[nt][1], c[nt][2], c[nt][3],
                    a0[0], a0[1], a0[2], a0[3], b0, b1);
            MMA_F16(c[nt][0], c[nt][1], c[nt][2], c[nt][3],
                    a1[0], a1[1], a1[2], a1[3], b2, b3);
        }
        __syncthreads();
    }

    const int mrow = m0 + wm * 16 + (lane >> 2);
    #pragma unroll
    for (int nt = 0; nt < 8; nt++) {
        const int o = n0 + wn * 64 + nt * 8 + 2 * (lane & 3);
        const float2 bias = *(const float2*)&bo[o];
        *(float2*)&out[(size_t)mrow * 256 + o] =
            make_float2(c[nt][0] + bias.x, c[nt][1] + bias.y);
        *(float2*)&out[(size_t)(mrow + 8) * 256 + o] =
            make_float2(c[nt][2] + bias.x, c[nt][3] + bias.y);
    }
}

// ---------------- launch ---------------------------------------------------
extern "C" void kernel_launch(void* const* d_in, const int* in_sizes, int n_in,
                              void* d_out, int out_size)
{
    const float* x   = (const float*)d_in[0];
    const float* adj = (const float*)d_in[1];
    const float* Wq  = (const float*)d_in[2];
    const float* Wk  = (const float*)d_in[3];
    const float* Wv  = (const float*)d_in[4];
    const float* Wo  = (const float*)d_in[5];
    const float* bo  = (const float*)d_in[6];
    float* out = (float*)d_out;

    prep_kernel<<<1024, 256>>>(x, Wq, Wk, Wv, Wo, adj);
    qkvh_kernel<<<dim3(MROWS / 64, 2, 3), 256>>>();
    attn_kernel<<<BH * NTILE, 256>>>();
    oprojh_kernel<<<dim3(MROWS / 64, 2), 256>>>(bo, out);
}